// round 9
// baseline (speedup 1.0000x reference)
#include <cuda_runtime.h>

#define NPTS   8192
#define NUM_ITER 5
#define INVB   0.2f    // 1/BETA
#define INV2S  0.02f   // 1/(2*5^2) shared spatial bandwidth (ALPHA == GAMMA == 5)
#define NF     21      // Taylor features, total degree <= 5
#define NFU    22      // + 1 spatial unit
#define NBLK   444     // 3 blocks/SM x 148 SMs -> all co-resident
#define NTHR   256
#define NABT   (NFU * 16)   // 352 AB tasks (one round)

__constant__ int FM[NF] = {0, 0,1, 0,1,2, 0,1,2,3, 0,1,2,3,4, 0,1,2,3,4,5};
__constant__ int FN[NF] = {0, 1,0, 2,1,0, 3,2,1,0, 4,3,2,1,0, 5,4,3,2,1,0};
__constant__ float FACT[6] = {1.f,1.f,2.f,6.f,24.f,120.f};

// Device scratch (allocation-free per harness rules)
__device__ float2 g_m12[NPTS];         // m1, m2
__device__ float4 g_wb[NPTS];          // bilateral input (g*m1*q)
__device__ float4 g_ws[NPTS];          // spatial input  (m2*q)
__device__ float4 g_F4[NFU * NPTS];    // x+y-filtered maps, [u][z*512 + x*16 + y]
__device__ unsigned int g_barc;        // grid barrier arrival count
__device__ volatile unsigned int g_barg; // grid barrier generation

__device__ __forceinline__ void gsync(unsigned int* gen) {
    __syncthreads();
    if (threadIdx.x == 0) {
        __threadfence();
        unsigned int target = *gen + 1;
        if (atomicAdd(&g_barc, 1u) == NBLK - 1) {
            g_barc = 0;
            __threadfence();
            g_barg = target;
        } else {
            while (g_barg != target) __nanosleep(32);
            __threadfence();
        }
        *gen = target;
    }
    __syncthreads();
}

__device__ __forceinline__ float4 softmax4(float4 l) {
    float m = fmaxf(fmaxf(l.x, l.y), fmaxf(l.z, l.w));
    float e0 = __expf(l.x - m), e1 = __expf(l.y - m);
    float e2 = __expf(l.z - m), e3 = __expf(l.w - m);
    float s = 1.0f / (e0 + e1 + e2 + e3);
    return make_float4(e0 * s, e1 * s, e2 * s, e3 * s);
}

__device__ __forceinline__ float phi_u(int u, float u1, float u2) {
    int m = FM[u], n = FN[u];
    float p = rsqrtf(FACT[m] * FACT[n]);
    for (int t = 0; t < m; t++) p *= u1;
    for (int t = 0; t < n; t++) p *= u2;
    return p;
}

__shared__ union {
    struct { float4 sa[512]; float4 sb[512]; } ab;
    struct { float4 tile[256]; float4 red[256]; float4 ssp[32]; } cz;
} sh;
__shared__ float Wd[32];
__shared__ float wc[16];

// AB phase: expand unit u, x-filter, y-filter for slice z. 352 tasks, ONE round.
__device__ __forceinline__ void ab_phase(int b, int t, int mode,
                                         const float* __restrict__ feat) {
    if (b >= NABT) return;
    int u = b >> 4, z = b & 15;
    #pragma unroll
    for (int h = 0; h < 2; h++) {
        int p = t + 256 * h;
        int x = p >> 4, y = p & 15;
        int i = x * 256 + y * 16 + z;
        float4 in;
        if (u < NF) {
            float u1 = feat[i] * INVB, u2 = feat[NPTS + i] * INVB;
            float ph = phi_u(u, u1, u2);
            if (mode == 0) {
                float g = __expf(-0.5f * (u1 * u1 + u2 * u2));
                float v = ph * g;
                in = make_float4(v, v, v, v);
            } else {
                float4 wb = g_wb[i];
                in = make_float4(ph * wb.x, ph * wb.y, ph * wb.z, ph * wb.w);
            }
        } else {
            in = (mode == 0) ? make_float4(1.f, 1.f, 1.f, 1.f) : g_ws[i];
        }
        sh.ab.sa[p] = in;
    }
    __syncthreads();
    #pragma unroll
    for (int h = 0; h < 2; h++) {
        int p = t + 256 * h;
        int x = p >> 4, y = p & 15;
        float4 a = make_float4(0.f, 0.f, 0.f, 0.f);
        #pragma unroll
        for (int xp = 0; xp < 32; xp++) {
            int d = x - xp; if (d < 0) d = -d;
            float w = Wd[d];
            float4 v = sh.ab.sa[xp * 16 + y];
            a.x += w * v.x; a.y += w * v.y; a.z += w * v.z; a.w += w * v.w;
        }
        sh.ab.sb[p] = a;
    }
    __syncthreads();
    #pragma unroll
    for (int h = 0; h < 2; h++) {
        int p = t + 256 * h;
        int x = p >> 4, y = p & 15;
        float4 bb = make_float4(0.f, 0.f, 0.f, 0.f);
        #pragma unroll
        for (int yp = 0; yp < 16; yp++) {
            int d = y - yp; if (d < 0) d = -d;
            float w = Wd[d];
            float4 v = sh.ab.sb[x * 16 + yp];
            bb.x += w * v.x; bb.y += w * v.y; bb.z += w * v.z; bb.w += w * v.w;
        }
        g_F4[u * NPTS + z * 512 + p] = bb;
    }
}

// CZF phase: z-filter + projection + fused F update. Blocks 0..255 active;
// block = (x, y-pair) owns 32 points across all units (8 units per round).
__device__ __forceinline__ void czf_phase(int b, int t, int mode, int last,
                                          const float* __restrict__ lu,
                                          const float* __restrict__ feat,
                                          float* __restrict__ out) {
    if (b >= 256) return;
    int x = b >> 3, y0 = (b & 7) * 2;
    int ul = t >> 5, p = t & 31;
    int yl = p >> 4, zl = p & 15;
    int y = y0 + yl, z = zl;
    int i = x * 256 + y * 16 + z;
    float u1 = feat[i] * INVB, u2 = feat[NPTS + i] * INVB;
    float4 acc = make_float4(0.f, 0.f, 0.f, 0.f);
    for (int ur = 0; ur < 24; ur += 8) {
        int u = ur + ul;
        if (u < NFU)
            sh.cz.tile[t] = g_F4[u * NPTS + zl * 512 + x * 16 + y];
        __syncthreads();
        if (u < NFU) {
            float4 zf = make_float4(0.f, 0.f, 0.f, 0.f);
            #pragma unroll
            for (int zp = 0; zp < 16; zp++) {
                int d = z - zp; if (d < 0) d = -d;
                float w = Wd[d];
                float4 v = sh.cz.tile[ul * 32 + yl * 16 + zp];
                zf.x += w * v.x; zf.y += w * v.y; zf.z += w * v.z; zf.w += w * v.w;
            }
            if (u < NF) {
                float ph = phi_u(u, u1, u2);
                acc.x += ph * zf.x; acc.y += ph * zf.y;
                acc.z += ph * zf.z; acc.w += ph * zf.w;
            } else {
                sh.cz.ssp[p] = zf;   // spatial unit (u == NF)
            }
        }
        __syncthreads();
    }
    sh.cz.red[t] = acc;
    __syncthreads();
    if (t < 128) { float4 o = sh.cz.red[t + 128];
        sh.cz.red[t].x += o.x; sh.cz.red[t].y += o.y; sh.cz.red[t].z += o.z; sh.cz.red[t].w += o.w; }
    __syncthreads();
    if (t < 64) { float4 o = sh.cz.red[t + 64];
        sh.cz.red[t].x += o.x; sh.cz.red[t].y += o.y; sh.cz.red[t].z += o.z; sh.cz.red[t].w += o.w; }
    __syncthreads();
    if (t < 32) {
        float4 proj = sh.cz.red[t];
        float4 o = sh.cz.red[t + 32];
        proj.x += o.x; proj.y += o.y; proj.z += o.z; proj.w += o.w;
        float4 sp = sh.cz.ssp[t];
        int yy = y0 + (t >> 4), zz = t & 15;
        int ii = x * 256 + yy * 16 + zz;
        float f1 = feat[ii] * INVB, f2 = feat[NPTS + ii] * INVB;
        float gg = __expf(-0.5f * (f1 * f1 + f2 * f2));
        float4 l = make_float4(lu[ii], lu[NPTS + ii], lu[2 * NPTS + ii], lu[3 * NPTS + ii]);
        if (mode == 0) {
            float m1 = rsqrtf(gg * proj.x);   // K1 row sum
            float m2 = rsqrtf(sp.x);          // K2 row sum
            g_m12[ii] = make_float2(m1, m2);
            float4 q = softmax4(l);
            float c1 = gg * m1;
            g_wb[ii] = make_float4(q.x * c1, q.y * c1, q.z * c1, q.w * c1);
            g_ws[ii] = make_float4(q.x * m2, q.y * m2, q.z * m2, q.w * m2);
        } else {
            float2 m = g_m12[ii];
            float c1 = gg * m.x;
            float4 qc;
            qc.x = c1 * proj.x + m.y * sp.x;
            qc.y = c1 * proj.y + m.y * sp.y;
            qc.z = c1 * proj.z + m.y * sp.z;
            qc.w = c1 * proj.w + m.y * sp.w;
            l.x -= wc[0]  * qc.x + wc[1]  * qc.y + wc[2]  * qc.z + wc[3]  * qc.w;
            l.y -= wc[4]  * qc.x + wc[5]  * qc.y + wc[6]  * qc.z + wc[7]  * qc.w;
            l.z -= wc[8]  * qc.x + wc[9]  * qc.y + wc[10] * qc.z + wc[11] * qc.w;
            l.w -= wc[12] * qc.x + wc[13] * qc.y + wc[14] * qc.z + wc[15] * qc.w;
            float4 q = softmax4(l);
            g_wb[ii] = make_float4(q.x * c1, q.y * c1, q.z * c1, q.w * c1);
            g_ws[ii] = make_float4(q.x * m.y, q.y * m.y, q.z * m.y, q.w * m.y);
            if (last) {
                out[ii]            = q.x;
                out[NPTS + ii]     = q.y;
                out[2 * NPTS + ii] = q.z;
                out[3 * NPTS + ii] = q.w;
            }
        }
    }
}

__global__ void __launch_bounds__(NTHR, 3)
crf_kernel(const float* __restrict__ lu, const float* __restrict__ feat,
           const float* __restrict__ W, float* __restrict__ out) {
    int b = blockIdx.x, t = threadIdx.x;
    if (t < 32) Wd[t] = __expf(-INV2S * (float)(t * t));
    if (t < 16) wc[t] = W[t];
    __syncthreads();
    unsigned int gen = g_barg;

    // Norm pass (inputs derived inline from feat)
    ab_phase(b, t, 0, feat);
    gsync(&gen);
    czf_phase(b, t, 0, 0, lu, feat, out);
    gsync(&gen);

    // Mean-field iterations
    for (int it = 0; it < NUM_ITER; it++) {
        ab_phase(b, t, 1, feat);
        gsync(&gen);
        czf_phase(b, t, 1, it == NUM_ITER - 1 ? 1 : 0, lu, feat, out);
        if (it != NUM_ITER - 1) gsync(&gen);
    }
}

extern "C" void kernel_launch(void* const* d_in, const int* in_sizes, int n_in,
                              void* d_out, int out_size) {
    const float* lu   = (const float*)d_in[0];
    const float* feat = (const float*)d_in[1];
    const float* comp = (const float*)d_in[2];
    float* out = (float*)d_out;
    crf_kernel<<<NBLK, NTHR>>>(lu, feat, comp, out);
}